// round 8
// baseline (speedup 1.0000x reference)
#include <cuda_runtime.h>
#include <cuda_bf16.h>
#include <cstdint>

namespace {
constexpr int D=128, D2=256, NFEAT=9, VOC=100, KS=3, LAY=3, NPAD=100096;
constexpr int EMAX=600000;
constexpr int BM=128, BN=128, BK=32;
constexpr int OFF_ARAW=0, OFF_AH=32768, OFF_AL=53248, OFF_BH=73728, OFF_BL=91136;
constexpr int OFF_ST=110592;                 // 2*128 floats for fused stats
constexpr int SMEM_BYTES=111616;
}

__device__ float g_h   [NPAD * D];
__device__ float g_agg [KS * NPAD * D];
__device__ float g_y1  [KS * NPAD * D2];
__device__ float g_zc  [NPAD * D2];
__device__ float g_hacc[NPAD * D];
__device__ float g_sum  [KS * D2];
__device__ float g_sq   [KS * D2];
__device__ float g_scale[KS * D2];
__device__ float g_shift[KS * D2];
__device__ float g_aw   [KS];
__device__ __align__(16) __nv_bfloat16 g_W1h[LAY * D * D2];
__device__ __align__(16) __nv_bfloat16 g_W1l[LAY * D * D2];
__device__ __align__(16) __nv_bfloat16 g_W2h[LAY * D2 * D];
__device__ __align__(16) __nv_bfloat16 g_W2l[LAY * D2 * D];
// CSR scratch (built once per launch; edges constant across layers)
__device__ int g_deg   [KS * NPAD];
__device__ int g_dcur  [KS * NPAD];
__device__ int g_rowptr[KS * (NPAD + 1)];
__device__ int g_csrc  [KS * EMAX];

// ---------------- PTX helpers ----------------
__device__ __forceinline__ uint32_t smem_u32(const void* p){return (uint32_t)__cvta_generic_to_shared(p);}
__device__ __forceinline__ void ldsm_x4(uint32_t r[4], uint32_t a){
    asm volatile("ldmatrix.sync.aligned.m8n8.x4.shared.b16 {%0,%1,%2,%3},[%4];"
                 :"=r"(r[0]),"=r"(r[1]),"=r"(r[2]),"=r"(r[3]):"r"(a));
}
__device__ __forceinline__ void ldsm_x4t(uint32_t r[4], uint32_t a){
    asm volatile("ldmatrix.sync.aligned.m8n8.x4.trans.shared.b16 {%0,%1,%2,%3},[%4];"
                 :"=r"(r[0]),"=r"(r[1]),"=r"(r[2]),"=r"(r[3]):"r"(a));
}
__device__ __forceinline__ void mma16816(float c[4], const uint32_t a[4], const uint32_t* b){
    asm volatile("mma.sync.aligned.m16n8k16.row.col.f32.bf16.bf16.f32 "
                 "{%0,%1,%2,%3},{%4,%5,%6,%7},{%8,%9},{%0,%1,%2,%3};"
                 :"+f"(c[0]),"+f"(c[1]),"+f"(c[2]),"+f"(c[3])
                 :"r"(a[0]),"r"(a[1]),"r"(a[2]),"r"(a[3]),"r"(b[0]),"r"(b[1]));
}
__device__ __forceinline__ void cp16(void* d, const void* s){
    asm volatile("cp.async.cg.shared.global [%0],[%1],16;"::"r"(smem_u32(d)),"l"(s):"memory");
}

// ---------------- small kernels ----------------
__global__ void embed_kernel(const int* __restrict__ x, const float* __restrict__ emb,
                             float* __restrict__ H, int N)
{
    int gt = blockIdx.x*blockDim.x+threadIdx.x;
    int node = gt>>5, lane = gt&31;
    if (node >= N) return;
    float4 acc = make_float4(0.f,0.f,0.f,0.f);
#pragma unroll
    for (int f=0; f<NFEAT; f++){
        int idx = x[node*NFEAT+f];
        float4 v = ((const float4*)(emb + ((size_t)f*VOC+idx)*D))[lane];
        acc.x+=v.x; acc.y+=v.y; acc.z+=v.z; acc.w+=v.w;
    }
    ((float4*)(H+(size_t)node*D))[lane] = acc;
}

__global__ void softmax3_kernel(const float* __restrict__ alpha, float* __restrict__ a)
{
    float a0=alpha[0],a1=alpha[1],a2=alpha[2];
    float m=fmaxf(a0,fmaxf(a1,a2));
    float e0=expf(a0-m),e1=expf(a1-m),e2=expf(a2-m);
    float inv=1.f/(e0+e1+e2);
    a[0]=e0*inv; a[1]=e1*inv; a[2]=e2*inv;
}

__global__ void wsplit_kernel(const float* __restrict__ W1, const float* __restrict__ W2,
                              __nv_bfloat16* __restrict__ w1h, __nv_bfloat16* __restrict__ w1l,
                              __nv_bfloat16* __restrict__ w2h, __nv_bfloat16* __restrict__ w2l)
{
    int i = blockIdx.x*blockDim.x+threadIdx.x;
    const int tot = LAY*D*D2;
    if (i < tot){
        float v = W1[i];
        __nv_bfloat16 h = __float2bfloat16(v);
        w1h[i] = h;
        w1l[i] = __float2bfloat16(v-__bfloat162float(h));
    } else if (i < 2*tot){
        int j = i-tot;
        float v = W2[j];
        __nv_bfloat16 h = __float2bfloat16(v);
        w2h[j] = h;
        w2l[j] = __float2bfloat16(v-__bfloat162float(h));
    }
}

// ---------------- CSR build (once per launch) ----------------
__global__ void hist_kernel(const int* __restrict__ ke, int* __restrict__ deg, int E, int N)
{
    int i = blockIdx.x*blockDim.x+threadIdx.x;
    if (i >= KS*E) return;
    int k = i/E, e = i - k*E;
    int d = ke[(size_t)(k*2+1)*E + e];
    atomicAdd(&deg[k*N + d], 1);
}

__global__ void scan_kernel(const int* __restrict__ deg, int* __restrict__ rowptr,
                            int* __restrict__ dcur, int N, int E)
{
    const int T = 1024;
    int k = blockIdx.x, t = threadIdx.x;
    int chunk = (N + T - 1)/T;
    int lo = t*chunk, hi = min(lo+chunk, N);
    int s = 0;
    for (int i=lo; i<hi; i++) s += deg[k*N+i];
    __shared__ int ps[T];
    ps[t] = s;
    __syncthreads();
    for (int off=1; off<T; off<<=1){
        int v = (t>=off) ? ps[t-off] : 0;
        __syncthreads();
        ps[t] += v;
        __syncthreads();
    }
    int run = (t>0) ? ps[t-1] : 0;
    for (int i=lo; i<hi; i++){
        rowptr[k*(N+1)+i] = run;
        dcur[k*N+i] = run;
        run += deg[k*N+i];
    }
    if (t == 0) rowptr[k*(N+1)+N] = E;
}

__global__ void fill_kernel(const int* __restrict__ ke, int* __restrict__ dcur,
                            int* __restrict__ csrc, int E, int N)
{
    int i = blockIdx.x*blockDim.x+threadIdx.x;
    if (i >= KS*E) return;
    int k = i/E, e = i - k*E;
    int s = ke[(size_t)(k*2)*E + e];
    int d = ke[(size_t)(k*2+1)*E + e];
    int pos = atomicAdd(&dcur[k*N + d], 1);
    csrc[k*E + pos] = s;
}

// agg[k][node] = (1+eps)*h[node] + sum_{j in CSR(k,node)} h[src_j]
__global__ void aggregate_kernel(const float* __restrict__ H,
                                 const int* __restrict__ rowptr, const int* __restrict__ csrc,
                                 const float* __restrict__ epsp,
                                 float* __restrict__ Agg, int N, int E)
{
    int gw = (blockIdx.x*blockDim.x + threadIdx.x) >> 5;
    int lane = threadIdx.x & 31;
    int k = blockIdx.y;
    if (gw >= N) return;
    float se = 1.0f + epsp[0];
    float4 c = __ldg((const float4*)(H + (size_t)gw*D) + lane);
    c.x*=se; c.y*=se; c.z*=se; c.w*=se;
    int lo = __ldg(rowptr + k*(N+1) + gw);
    int hi = __ldg(rowptr + k*(N+1) + gw + 1);
    for (int j=lo; j<hi; j++){
        int s = __ldg(csrc + (size_t)k*E + j);
        float4 v = __ldg((const float4*)(H + (size_t)s*D) + lane);
        c.x+=v.x; c.y+=v.y; c.z+=v.z; c.w+=v.w;
    }
    ((float4*)(Agg + (size_t)k*NPAD*D + (size_t)gw*D))[lane] = c;
}

// ---------------------------------------------------------------------------
// Pipelined HMMA split-bf16 GEMM with fused column stats in epilogue.
//   CZ: per-z strides on A/C and stats (gemm1).  STATS: accumulate col sums.
// ---------------------------------------------------------------------------
template <int KTOT, int NTOT, bool CZ>
__global__ __launch_bounds__(256, 2) void tgemm_kernel(
    const float* __restrict__ A,
    const __nv_bfloat16* __restrict__ Bhp, const __nv_bfloat16* __restrict__ Blp,
    const float* __restrict__ bias,
    float* __restrict__ C, float* __restrict__ gsum, float* __restrict__ gsq, int M)
{
    extern __shared__ __align__(16) char dynsm[];
    float*         sAraw = (float*)        (dynsm+OFF_ARAW);
    __nv_bfloat16* sAh   = (__nv_bfloat16*)(dynsm+OFF_AH);
    __nv_bfloat16* sAl   = (__nv_bfloat16*)(dynsm+OFF_AL);
    __nv_bfloat16* sBh   = (__nv_bfloat16*)(dynsm+OFF_BH);
    __nv_bfloat16* sBl   = (__nv_bfloat16*)(dynsm+OFF_BL);
    float*         ssum  = (float*)        (dynsm+OFF_ST);
    float*         ssq   = ssum + 128;

    const int tid=threadIdx.x, wid=tid>>5, lane=tid&31;
    const int wm=wid>>1, wn=wid&1;
    const int rowBase=blockIdx.x*BM, colBase=blockIdx.y*BN;

    if (CZ){
        const int z = blockIdx.z;
        A += (size_t)z*NPAD*KTOT;
        C += (size_t)z*NPAD*NTOT;
        gsum += (size_t)z*NTOT;
        gsq  += (size_t)z*NTOT;
    }
    if (tid < 128){ ssum[tid]=0.f; ssq[tid]=0.f; }

    const int ar=tid>>3, acv=tid&7, br=tid>>4, bcv=tid&15;

    auto issue_tile=[&](int t,int s){
        const int kk=t*BK;
        float* aDst=sAraw+s*(128*32);
#pragma unroll
        for (int p=0;p<4;p++){
            int r=ar+p*32;
            cp16(aDst+r*32+acv*4, A+(size_t)(rowBase+r)*KTOT+kk+acv*4);
        }
        __nv_bfloat16* bhDst=sBh+s*(32*136);
        __nv_bfloat16* blDst=sBl+s*(32*136);
#pragma unroll
        for (int p=0;p<2;p++){
            int r=br+p*16;
            cp16(bhDst+r*136+bcv*8, Bhp+(size_t)(kk+r)*NTOT+colBase+bcv*8);
            cp16(blDst+r*136+bcv*8, Blp+(size_t)(kk+r)*NTOT+colBase+bcv*8);
        }
    };

    issue_tile(0,0);
    asm volatile("cp.async.commit_group;":::"memory");

    float acc[2][8][4];
#pragma unroll
    for (int m=0;m<2;m++)
#pragma unroll
        for (int n=0;n<8;n++)
#pragma unroll
            for (int q=0;q<4;q++) acc[m][n][q]=0.f;

    const int ktiles=KTOT/BK;
    for (int t=0;t<ktiles;t++){
        const int s=t&1;
        asm volatile("cp.async.wait_group 0;":::"memory");
        __syncthreads();
        if (t+1<ktiles){ issue_tile(t+1,s^1); asm volatile("cp.async.commit_group;":::"memory"); }
        {
            const float* aSrc=sAraw+s*(128*32);
            __nv_bfloat16* hDst=sAh+s*(128*40);
            __nv_bfloat16* lDst=sAl+s*(128*40);
#pragma unroll
            for (int p=0;p<4;p++){
                int r=ar+p*32;
                float4 v=*(const float4*)(aSrc+r*32+acv*4);
                float vv[4]={v.x,v.y,v.z,v.w};
#pragma unroll
                for (int j=0;j<4;j+=2){
                    __nv_bfloat16 h0=__float2bfloat16(vv[j]), h1=__float2bfloat16(vv[j+1]);
                    __nv_bfloat16 l0=__float2bfloat16(vv[j]-__bfloat162float(h0));
                    __nv_bfloat16 l1=__float2bfloat16(vv[j+1]-__bfloat162float(h1));
                    __nv_bfloat162 th; th.x=h0; th.y=h1;
                    __nv_bfloat162 tl; tl.x=l0; tl.y=l1;
                    *(__nv_bfloat162*)(hDst+r*40+acv*4+j)=th;
                    *(__nv_bfloat162*)(lDst+r*40+acv*4+j)=tl;
                }
            }
        }
        __syncthreads();
        const __nv_bfloat16 *ah_s=sAh+s*(128*40), *al_s=sAl+s*(128*40);
        const __nv_bfloat16 *bh_s=sBh+s*(32*136), *bl_s=sBl+s*(32*136);
#pragma unroll
        for (int kb=0;kb<BK/16;kb++){
            uint32_t ah[2][4], al[2][4], bf[8][2];
#pragma unroll
            for (int m=0;m<2;m++){
                int row=wm*32+m*16+(lane&15), col=kb*16+(lane>>4)*8;
                ldsm_x4(ah[m], smem_u32(ah_s+row*40+col));
                ldsm_x4(al[m], smem_u32(al_s+row*40+col));
            }
#pragma unroll
            for (int nb=0;nb<4;nb++){
                int row=kb*16+(lane&15), col=wn*64+nb*16+(lane>>4)*8;
                uint32_t tr[4];
                ldsm_x4t(tr, smem_u32(bh_s+row*136+col));
                bf[nb*2][0]=tr[0]; bf[nb*2][1]=tr[1];
                bf[nb*2+1][0]=tr[2]; bf[nb*2+1][1]=tr[3];
            }
#pragma unroll
            for (int m=0;m<2;m++)
#pragma unroll
                for (int n=0;n<8;n++){ mma16816(acc[m][n],ah[m],bf[n]); mma16816(acc[m][n],al[m],bf[n]); }
#pragma unroll
            for (int nb=0;nb<4;nb++){
                int row=kb*16+(lane&15), col=wn*64+nb*16+(lane>>4)*8;
                uint32_t tr[4];
                ldsm_x4t(tr, smem_u32(bl_s+row*136+col));
                bf[nb*2][0]=tr[0]; bf[nb*2][1]=tr[1];
                bf[nb*2+1][0]=tr[2]; bf[nb*2+1][1]=tr[3];
            }
#pragma unroll
            for (int m=0;m<2;m++)
#pragma unroll
                for (int n=0;n<8;n++) mma16816(acc[m][n],ah[m],bf[n]);
        }
    }

    // ---- store epilogue ----
#pragma unroll
    for (int m=0;m<2;m++){
        int rbase=rowBase+wm*32+m*16+(lane>>2);
#pragma unroll
        for (int half=0;half<2;half++){
            int rr=rbase+half*8;
            if (rr<M){
#pragma unroll
                for (int n=0;n<8;n++){
                    int c=colBase+wn*64+n*8+(lane&3)*2;
                    float2 o;
                    o.x=acc[m][n][half*2+0]+bias[c];
                    o.y=acc[m][n][half*2+1]+bias[c+1];
                    *(float2*)(C+(size_t)rr*NTOT+c)=o;
                }
            }
        }
    }
    // ---- fused column stats (sum, sumsq over valid rows) ----
    __syncthreads();
#pragma unroll
    for (int n=0;n<8;n++){
#pragma unroll
        for (int j=0;j<2;j++){
            float s_=0.f, q_=0.f;
#pragma unroll
            for (int m=0;m<2;m++){
#pragma unroll
                for (int half=0; half<2; half++){
                    int rr = rowBase+wm*32+m*16+(lane>>2)+half*8;
                    if (rr<M){
                        float v = acc[m][n][half*2+j] + bias[colBase+wn*64+n*8+(lane&3)*2+j];
                        s_ += v; q_ += v*v;
                    }
                }
            }
            int lc = wn*64+n*8+(lane&3)*2+j;
            atomicAdd(&ssum[lc], s_);
            atomicAdd(&ssq[lc],  q_);
        }
    }
    __syncthreads();
    if (tid < 128){
        atomicAdd(gsum + colBase + tid, ssum[tid]);
        atomicAdd(gsq  + colBase + tid, ssq[tid]);
    }
}

// zc = sum_k aw[k] * relu( y1_k * scale_k + shift_k )
__global__ void combine_kernel(const float* __restrict__ Y1, const float* __restrict__ scale,
                               const float* __restrict__ shift, const float* __restrict__ aw,
                               float* __restrict__ Zc, int n4)
{
    int i = blockIdx.x*blockDim.x+threadIdx.x;
    if (i >= n4) return;
    int c4 = i & 63;
    float4 acc = make_float4(0.f,0.f,0.f,0.f);
    const int zs = NPAD*(D2/4);
#pragma unroll
    for (int k=0;k<KS;k++){
        float a = __ldg(aw+k);
        float4 v  = __ldg((const float4*)Y1 + (size_t)k*zs + i);
        float4 sc = __ldg((const float4*)(scale+k*D2)+c4);
        float4 sh = __ldg((const float4*)(shift+k*D2)+c4);
        acc.x += a*fmaxf(fmaf(v.x,sc.x,sh.x),0.f);
        acc.y += a*fmaxf(fmaf(v.y,sc.y,sh.y),0.f);
        acc.z += a*fmaxf(fmaf(v.z,sc.z,sh.z),0.f);
        acc.w += a*fmaxf(fmaf(v.w,sc.w,sh.w),0.f);
    }
    ((float4*)Zc)[i] = acc;
}

__global__ void finalize_kernel(const float* __restrict__ s, const float* __restrict__ q,
                                const float* __restrict__ g, const float* __restrict__ b,
                                float* __restrict__ scale, float* __restrict__ shift,
                                float invN, int C)
{
    int k = blockIdx.x, c = threadIdx.x;
    float mu = s[k*C+c]*invN;
    float var = q[k*C+c]*invN - mu*mu;
    float rstd = rsqrtf(var+1e-5f);
    float sc = rstd*g[c];
    scale[k*C+c] = sc;
    shift[k*C+c] = b[c]-mu*sc;
}

__global__ void bnrelu_kernel(const float* __restrict__ X, const float* __restrict__ scale,
                              const float* __restrict__ shift, float* __restrict__ Out, int n4)
{
    int i = blockIdx.x*blockDim.x+threadIdx.x;
    if (i >= n4) return;
    int c4 = i & 31;
    float4 v  = ((const float4*)X)[i];
    float4 sc = ((const float4*)scale)[c4];
    float4 sh = ((const float4*)shift)[c4];
    v.x=fmaxf(fmaf(v.x,sc.x,sh.x),0.f);
    v.y=fmaxf(fmaf(v.y,sc.y,sh.y),0.f);
    v.z=fmaxf(fmaf(v.z,sc.z,sh.z),0.f);
    v.w=fmaxf(fmaf(v.w,sc.w,sh.w),0.f);
    ((float4*)Out)[i] = v;
}

// ---------------------------------------------------------------------------
extern "C" void kernel_launch(void* const* d_in, const int* in_sizes, int n_in,
                              void* d_out, int out_size)
{
    const int*   x     = (const int*)  d_in[0];
    const int*   ke    = (const int*)  d_in[1];
    const float* emb   = (const float*)d_in[2];
    const float* W1    = (const float*)d_in[3];
    const float* b1    = (const float*)d_in[4];
    const float* g1    = (const float*)d_in[5];
    const float* be1   = (const float*)d_in[6];
    const float* W2    = (const float*)d_in[7];
    const float* b2    = (const float*)d_in[8];
    const float* eps   = (const float*)d_in[9];
    const float* alpha = (const float*)d_in[10];
    const float* bn_g  = (const float*)d_in[11];
    const float* bn_b  = (const float*)d_in[12];

    const int N = in_sizes[0]/NFEAT;
    const int E = in_sizes[1]/(KS*2);
    const int n4  = N*(D/4);
    const int n4b = N*(D2/4);
    const int nTilesM = (N+BM-1)/BM;

    float *p_h,*p_agg,*p_y1,*p_zc,*p_hacc,*p_sum,*p_sq,*p_scale,*p_shift,*p_aw;
    __nv_bfloat16 *p_w1h,*p_w1l,*p_w2h,*p_w2l;
    int *p_deg,*p_dcur,*p_rowptr,*p_csrc;
    cudaGetSymbolAddress((void**)&p_h,g_h);
    cudaGetSymbolAddress((void**)&p_agg,g_agg);
    cudaGetSymbolAddress((void**)&p_y1,g_y1);
    cudaGetSymbolAddress((void**)&p_zc,g_zc);
    cudaGetSymbolAddress((void**)&p_hacc,g_hacc);
    cudaGetSymbolAddress((void**)&p_sum,g_sum);
    cudaGetSymbolAddress((void**)&p_sq,g_sq);
    cudaGetSymbolAddress((void**)&p_scale,g_scale);
    cudaGetSymbolAddress((void**)&p_shift,g_shift);
    cudaGetSymbolAddress((void**)&p_aw,g_aw);
    cudaGetSymbolAddress((void**)&p_w1h,g_W1h);
    cudaGetSymbolAddress((void**)&p_w1l,g_W1l);
    cudaGetSymbolAddress((void**)&p_w2h,g_W2h);
    cudaGetSymbolAddress((void**)&p_w2l,g_W2l);
    cudaGetSymbolAddress((void**)&p_deg,g_deg);
    cudaGetSymbolAddress((void**)&p_dcur,g_dcur);
    cudaGetSymbolAddress((void**)&p_rowptr,g_rowptr);
    cudaGetSymbolAddress((void**)&p_csrc,g_csrc);

    cudaFuncSetAttribute(tgemm_kernel<D,  D2, true >,
                         cudaFuncAttributeMaxDynamicSharedMemorySize, SMEM_BYTES);
    cudaFuncSetAttribute(tgemm_kernel<D2, D,  false>,
                         cudaFuncAttributeMaxDynamicSharedMemorySize, SMEM_BYTES);

    const float invN = 1.0f/(float)N;

    // weights split (hi/lo bf16 planes)
    {
        int tot = 2*LAY*D*D2;
        wsplit_kernel<<<(tot+255)/256, 256>>>(W1, W2, p_w1h, p_w1l, p_w2h, p_w2l);
    }
    // CSR build (once per launch; edge sets constant across layers)
    cudaMemsetAsync(p_deg, 0, (size_t)KS*N*sizeof(int));
    hist_kernel<<<(KS*E+255)/256, 256>>>(ke, p_deg, E, N);
    scan_kernel<<<KS, 1024>>>(p_deg, p_rowptr, p_dcur, N, E);
    fill_kernel<<<(KS*E+255)/256, 256>>>(ke, p_dcur, p_csrc, E, N);

    embed_kernel<<<(N*32+255)/256, 256>>>(x, emb, p_h, N);

    for (int l = 0; l < LAY; l++){
        softmax3_kernel<<<1,1>>>(alpha+l*KS, p_aw);

        // agg[z] = (1+eps)h + CSR-gathered neighbor sum (no atomics)
        aggregate_kernel<<<dim3((N*32+255)/256, KS), 256>>>(
            p_h, p_rowptr, p_csrc, eps+l, p_agg, N, E);

        // y1[z] = agg[z] @ W1 + b1   (+fused per-z column stats)
        cudaMemsetAsync(p_sum, 0, KS*D2*sizeof(float));
        cudaMemsetAsync(p_sq,  0, KS*D2*sizeof(float));
        tgemm_kernel<D, D2, true><<<dim3(nTilesM, 2, KS), 256, SMEM_BYTES>>>(
            p_agg, p_w1h+(size_t)l*D*D2, p_w1l+(size_t)l*D*D2,
            b1+l*D2, p_y1, p_sum, p_sq, N);
        finalize_kernel<<<KS, D2>>>(p_sum, p_sq, g1+l*D2, be1+l*D2, p_scale, p_shift, invN, D2);

        // zc = sum_k aw[k] * relu(BN_k(y1_k))
        combine_kernel<<<(n4b+255)/256, 256>>>(p_y1, p_scale, p_shift, p_aw, p_zc, n4b);

        // hacc = zc @ W2 + b2   (+fused column stats)
        cudaMemsetAsync(p_sum, 0, D*sizeof(float));
        cudaMemsetAsync(p_sq,  0, D*sizeof(float));
        tgemm_kernel<D2, D, false><<<dim3(nTilesM,1,1), 256, SMEM_BYTES>>>(
            p_zc, p_w2h+(size_t)l*D2*D, p_w2l+(size_t)l*D2*D,
            b2+l*D, p_hacc, p_sum, p_sq, N);
        finalize_kernel<<<1, D>>>(p_sum, p_sq, bn_g+l*D, bn_b+l*D, p_scale, p_shift, invN, D);

        float* outp = (l == LAY-1) ? (float*)d_out : p_h;
        bnrelu_kernel<<<(n4+255)/256, 256>>>(p_hacc, p_scale, p_shift, outp, n4);
    }
}

// round 9
// speedup vs baseline: 1.2680x; 1.2680x over previous
#include <cuda_runtime.h>
#include <cuda_bf16.h>
#include <cstdint>

namespace {
constexpr int D=128, D2=256, NFEAT=9, VOC=100, KS=3, LAY=3, NPAD=100096;
constexpr int EMAX=600000;
constexpr int BM=128, BN=128, BK=32;
constexpr int OFF_ARAW=0, OFF_AH=32768, OFF_AL=53248, OFF_BH=73728, OFF_BL=91136;
constexpr int SMEM_BYTES=110592;
}

__device__ float g_h   [NPAD * D];
__device__ float g_agg [KS * NPAD * D];
__device__ float g_y1  [KS * NPAD * D2];
__device__ float g_zc  [NPAD * D2];
__device__ float g_hacc[NPAD * D];
__device__ float g_sum  [KS * D2];
__device__ float g_sq   [KS * D2];
__device__ float g_scale[KS * D2];
__device__ float g_shift[KS * D2];
__device__ float g_aw   [KS];
__device__ __align__(16) __nv_bfloat16 g_W1h[LAY * D * D2];
__device__ __align__(16) __nv_bfloat16 g_W1l[LAY * D * D2];
__device__ __align__(16) __nv_bfloat16 g_W2h[LAY * D2 * D];
__device__ __align__(16) __nv_bfloat16 g_W2l[LAY * D2 * D];
// CSR scratch (built once per launch; edge sets constant across layers)
__device__ int g_deg   [KS * NPAD];
__device__ int g_dcur  [KS * NPAD];
__device__ int g_rowptr[KS * (NPAD + 1)];
__device__ int g_csrc  [KS * EMAX];

// ---------------- PTX helpers ----------------
__device__ __forceinline__ uint32_t smem_u32(const void* p){return (uint32_t)__cvta_generic_to_shared(p);}
__device__ __forceinline__ void ldsm_x4(uint32_t r[4], uint32_t a){
    asm volatile("ldmatrix.sync.aligned.m8n8.x4.shared.b16 {%0,%1,%2,%3},[%4];"
                 :"=r"(r[0]),"=r"(r[1]),"=r"(r[2]),"=r"(r[3]):"r"(a));
}
__device__ __forceinline__ void ldsm_x4t(uint32_t r[4], uint32_t a){
    asm volatile("ldmatrix.sync.aligned.m8n8.x4.trans.shared.b16 {%0,%1,%2,%3},[%4];"
                 :"=r"(r[0]),"=r"(r[1]),"=r"(r[2]),"=r"(r[3]):"r"(a));
}
__device__ __forceinline__ void mma16816(float c[4], const uint32_t a[4], const uint32_t* b){
    asm volatile("mma.sync.aligned.m16n8k16.row.col.f32.bf16.bf16.f32 "
                 "{%0,%1,%2,%3},{%4,%5,%6,%7},{%8,%9},{%0,%1,%2,%3};"
                 :"+f"(c[0]),"+f"(c[1]),"+f"(c[2]),"+f"(c[3])
                 :"r"(a[0]),"r"(a[1]),"r"(a[2]),"r"(a[3]),"r"(b[0]),"r"(b[1]));
}
__device__ __forceinline__ void cp16(void* d, const void* s){
    asm volatile("cp.async.cg.shared.global [%0],[%1],16;"::"r"(smem_u32(d)),"l"(s):"memory");
}

// ---------------- small kernels ----------------
__global__ void embed_kernel(const int* __restrict__ x, const float* __restrict__ emb,
                             float* __restrict__ H, int N)
{
    int gt = blockIdx.x*blockDim.x+threadIdx.x;
    int node = gt>>5, lane = gt&31;
    if (node >= N) return;
    float4 acc = make_float4(0.f,0.f,0.f,0.f);
#pragma unroll
    for (int f=0; f<NFEAT; f++){
        int idx = x[node*NFEAT+f];
        float4 v = ((const float4*)(emb + ((size_t)f*VOC+idx)*D))[lane];
        acc.x+=v.x; acc.y+=v.y; acc.z+=v.z; acc.w+=v.w;
    }
    ((float4*)(H+(size_t)node*D))[lane] = acc;
}

__global__ void softmax3_kernel(const float* __restrict__ alpha, float* __restrict__ a)
{
    float a0=alpha[0],a1=alpha[1],a2=alpha[2];
    float m=fmaxf(a0,fmaxf(a1,a2));
    float e0=expf(a0-m),e1=expf(a1-m),e2=expf(a2-m);
    float inv=1.f/(e0+e1+e2);
    a[0]=e0*inv; a[1]=e1*inv; a[2]=e2*inv;
}

__global__ void wsplit_kernel(const float* __restrict__ W1, const float* __restrict__ W2,
                              __nv_bfloat16* __restrict__ w1h, __nv_bfloat16* __restrict__ w1l,
                              __nv_bfloat16* __restrict__ w2h, __nv_bfloat16* __restrict__ w2l)
{
    int i = blockIdx.x*blockDim.x+threadIdx.x;
    const int tot = LAY*D*D2;
    if (i < tot){
        float v = W1[i];
        __nv_bfloat16 h = __float2bfloat16(v);
        w1h[i] = h;
        w1l[i] = __float2bfloat16(v-__bfloat162float(h));
    } else if (i < 2*tot){
        int j = i-tot;
        float v = W2[j];
        __nv_bfloat16 h = __float2bfloat16(v);
        w2h[j] = h;
        w2l[j] = __float2bfloat16(v-__bfloat162float(h));
    }
}

// ---------------- CSR build (once per launch) ----------------
__global__ void hist_kernel(const int* __restrict__ ke, int* __restrict__ deg, int E, int N)
{
    int i = blockIdx.x*blockDim.x+threadIdx.x;
    if (i >= KS*E) return;
    int k = i/E, e = i - k*E;
    int d = ke[(size_t)(k*2+1)*E + e];
    atomicAdd(&deg[k*N + d], 1);
}

__global__ void scan_kernel(const int* __restrict__ deg, int* __restrict__ rowptr,
                            int* __restrict__ dcur, int N, int E)
{
    const int T = 1024;
    int k = blockIdx.x, t = threadIdx.x;
    int chunk = (N + T - 1)/T;
    int lo = t*chunk, hi = min(lo+chunk, N);
    int s = 0;
    for (int i=lo; i<hi; i++) s += deg[k*N+i];
    __shared__ int ps[T];
    ps[t] = s;
    __syncthreads();
    for (int off=1; off<T; off<<=1){
        int v = (t>=off) ? ps[t-off] : 0;
        __syncthreads();
        ps[t] += v;
        __syncthreads();
    }
    int run = (t>0) ? ps[t-1] : 0;
    for (int i=lo; i<hi; i++){
        rowptr[k*(N+1)+i] = run;
        dcur[k*N+i] = run;
        run += deg[k*N+i];
    }
    if (t == 0) rowptr[k*(N+1)+N] = E;
}

__global__ void fill_kernel(const int* __restrict__ ke, int* __restrict__ dcur,
                            int* __restrict__ csrc, int E, int N)
{
    int i = blockIdx.x*blockDim.x+threadIdx.x;
    if (i >= KS*E) return;
    int k = i/E, e = i - k*E;
    int s = ke[(size_t)(k*2)*E + e];
    int d = ke[(size_t)(k*2+1)*E + e];
    int pos = atomicAdd(&dcur[k*N + d], 1);
    csrc[k*E + pos] = s;
}

// agg[k][node] = (1+eps)*h[node] + sum_{j in CSR(k,node)} h[src_j]
// One warp per (node, k); 4-wide unroll for MLP.
__global__ void aggregate_kernel(const float* __restrict__ H,
                                 const int* __restrict__ rowptr, const int* __restrict__ csrc,
                                 const float* __restrict__ epsp,
                                 float* __restrict__ Agg, int N, int E)
{
    int gw = (blockIdx.x*blockDim.x + threadIdx.x) >> 5;
    int lane = threadIdx.x & 31;
    int k = blockIdx.y;
    if (gw >= N) return;
    float se = 1.0f + epsp[0];
    float4 c = __ldg((const float4*)(H + (size_t)gw*D) + lane);
    c.x*=se; c.y*=se; c.z*=se; c.w*=se;
    const int* cs = csrc + (size_t)k*E;
    int lo = __ldg(rowptr + k*(N+1) + gw);
    int hi = __ldg(rowptr + k*(N+1) + gw + 1);
    int j = lo;
    for (; j + 4 <= hi; j += 4){
        int s0=__ldg(cs+j), s1=__ldg(cs+j+1), s2=__ldg(cs+j+2), s3=__ldg(cs+j+3);
        float4 v0=__ldg((const float4*)(H+(size_t)s0*D)+lane);
        float4 v1=__ldg((const float4*)(H+(size_t)s1*D)+lane);
        float4 v2=__ldg((const float4*)(H+(size_t)s2*D)+lane);
        float4 v3=__ldg((const float4*)(H+(size_t)s3*D)+lane);
        c.x += (v0.x+v1.x)+(v2.x+v3.x);
        c.y += (v0.y+v1.y)+(v2.y+v3.y);
        c.z += (v0.z+v1.z)+(v2.z+v3.z);
        c.w += (v0.w+v1.w)+(v2.w+v3.w);
    }
    for (; j < hi; j++){
        int s = __ldg(cs+j);
        float4 v = __ldg((const float4*)(H+(size_t)s*D)+lane);
        c.x+=v.x; c.y+=v.y; c.z+=v.z; c.w+=v.w;
    }
    ((float4*)(Agg + (size_t)k*NPAD*D + (size_t)gw*D))[lane] = c;
}

// ---------------------------------------------------------------------------
// Pipelined HMMA split-bf16 GEMM (identical to the 2481us R5 version)
// ---------------------------------------------------------------------------
template <int KTOT, int NTOT, bool CZ>
__global__ __launch_bounds__(256, 2) void tgemm_kernel(
    const float* __restrict__ A,
    const __nv_bfloat16* __restrict__ Bhp, const __nv_bfloat16* __restrict__ Blp,
    const float* __restrict__ bias,
    float* __restrict__ C, int M)
{
    extern __shared__ __align__(16) char dynsm[];
    float*         sAraw = (float*)        (dynsm+OFF_ARAW);
    __nv_bfloat16* sAh   = (__nv_bfloat16*)(dynsm+OFF_AH);
    __nv_bfloat16* sAl   = (__nv_bfloat16*)(dynsm+OFF_AL);
    __nv_bfloat16* sBh   = (__nv_bfloat16*)(dynsm+OFF_BH);
    __nv_bfloat16* sBl   = (__nv_bfloat16*)(dynsm+OFF_BL);

    const int tid=threadIdx.x, wid=tid>>5, lane=tid&31;
    const int wm=wid>>1, wn=wid&1;
    const int rowBase=blockIdx.x*BM, colBase=blockIdx.y*BN;

    const float* Ap = A;
    float* Cp = C;
    if (CZ){
        const int z = blockIdx.z;
        Ap += (size_t)z*NPAD*KTOT;
        Cp += (size_t)z*NPAD*NTOT;
    }

    const int ar=tid>>3, acv=tid&7, br=tid>>4, bcv=tid&15;

    auto issue_tile=[&](int t,int s){
        const int kk=t*BK;
        float* aDst=sAraw+s*(128*32);
#pragma unroll
        for (int p=0;p<4;p++){
            int r=ar+p*32;
            cp16(aDst+r*32+acv*4, Ap+(size_t)(rowBase+r)*KTOT+kk+acv*4);
        }
        __nv_bfloat16* bhDst=sBh+s*(32*136);
        __nv_bfloat16* blDst=sBl+s*(32*136);
#pragma unroll
        for (int p=0;p<2;p++){
            int r=br+p*16;
            cp16(bhDst+r*136+bcv*8, Bhp+(size_t)(kk+r)*NTOT+colBase+bcv*8);
            cp16(blDst+r*136+bcv*8, Blp+(size_t)(kk+r)*NTOT+colBase+bcv*8);
        }
    };

    issue_tile(0,0);
    asm volatile("cp.async.commit_group;":::"memory");

    float acc[2][8][4];
#pragma unroll
    for (int m=0;m<2;m++)
#pragma unroll
        for (int n=0;n<8;n++)
#pragma unroll
            for (int q=0;q<4;q++) acc[m][n][q]=0.f;

    const int ktiles=KTOT/BK;
    for (int t=0;t<ktiles;t++){
        const int s=t&1;
        asm volatile("cp.async.wait_group 0;":::"memory");
        __syncthreads();
        if (t+1<ktiles){ issue_tile(t+1,s^1); asm volatile("cp.async.commit_group;":::"memory"); }
        {
            const float* aSrc=sAraw+s*(128*32);
            __nv_bfloat16* hDst=sAh+s*(128*40);
            __nv_bfloat16* lDst=sAl+s*(128*40);
#pragma unroll
            for (int p=0;p<4;p++){
                int r=ar+p*32;
                float4 v=*(const float4*)(aSrc+r*32+acv*4);
                float vv[4]={v.x,v.y,v.z,v.w};
#pragma unroll
                for (int j=0;j<4;j+=2){
                    __nv_bfloat16 h0=__float2bfloat16(vv[j]), h1=__float2bfloat16(vv[j+1]);
                    __nv_bfloat16 l0=__float2bfloat16(vv[j]-__bfloat162float(h0));
                    __nv_bfloat16 l1=__float2bfloat16(vv[j+1]-__bfloat162float(h1));
                    __nv_bfloat162 th; th.x=h0; th.y=h1;
                    __nv_bfloat162 tl; tl.x=l0; tl.y=l1;
                    *(__nv_bfloat162*)(hDst+r*40+acv*4+j)=th;
                    *(__nv_bfloat162*)(lDst+r*40+acv*4+j)=tl;
                }
            }
        }
        __syncthreads();
        const __nv_bfloat16 *ah_s=sAh+s*(128*40), *al_s=sAl+s*(128*40);
        const __nv_bfloat16 *bh_s=sBh+s*(32*136), *bl_s=sBl+s*(32*136);
#pragma unroll
        for (int kb=0;kb<BK/16;kb++){
            uint32_t ah[2][4], al[2][4], bf[8][2];
#pragma unroll
            for (int m=0;m<2;m++){
                int row=wm*32+m*16+(lane&15), col=kb*16+(lane>>4)*8;
                ldsm_x4(ah[m], smem_u32(ah_s+row*40+col));
                ldsm_x4(al[m], smem_u32(al_s+row*40+col));
            }
#pragma unroll
            for (int nb=0;nb<4;nb++){
                int row=kb*16+(lane&15), col=wn*64+nb*16+(lane>>4)*8;
                uint32_t tr[4];
                ldsm_x4t(tr, smem_u32(bh_s+row*136+col));
                bf[nb*2][0]=tr[0]; bf[nb*2][1]=tr[1];
                bf[nb*2+1][0]=tr[2]; bf[nb*2+1][1]=tr[3];
            }
#pragma unroll
            for (int m=0;m<2;m++)
#pragma unroll
                for (int n=0;n<8;n++){ mma16816(acc[m][n],ah[m],bf[n]); mma16816(acc[m][n],al[m],bf[n]); }
#pragma unroll
            for (int nb=0;nb<4;nb++){
                int row=kb*16+(lane&15), col=wn*64+nb*16+(lane>>4)*8;
                uint32_t tr[4];
                ldsm_x4t(tr, smem_u32(bl_s+row*136+col));
                bf[nb*2][0]=tr[0]; bf[nb*2][1]=tr[1];
                bf[nb*2+1][0]=tr[2]; bf[nb*2+1][1]=tr[3];
            }
#pragma unroll
            for (int m=0;m<2;m++)
#pragma unroll
                for (int n=0;n<8;n++) mma16816(acc[m][n],ah[m],bf[n]);
        }
    }

#pragma unroll
    for (int m=0;m<2;m++){
        int rbase=rowBase+wm*32+m*16+(lane>>2);
#pragma unroll
        for (int half=0;half<2;half++){
            int rr=rbase+half*8;
            if (rr<M){
#pragma unroll
                for (int n=0;n<8;n++){
                    int c=colBase+wn*64+n*8+(lane&3)*2;
                    float2 o;
                    o.x=acc[m][n][half*2+0]+bias[c];
                    o.y=acc[m][n][half*2+1]+bias[c+1];
                    *(float2*)(Cp+(size_t)rr*NTOT+c)=o;
                }
            }
        }
    }
}

// zc = sum_k aw[k] * relu( y1_k * scale_k + shift_k )
__global__ void combine_kernel(const float* __restrict__ Y1, const float* __restrict__ scale,
                               const float* __restrict__ shift, const float* __restrict__ aw,
                               float* __restrict__ Zc, int n4)
{
    int i = blockIdx.x*blockDim.x+threadIdx.x;
    if (i >= n4) return;
    int c4 = i & 63;
    float4 acc = make_float4(0.f,0.f,0.f,0.f);
    const int zs = NPAD*(D2/4);
#pragma unroll
    for (int k=0;k<KS;k++){
        float a = __ldg(aw+k);
        float4 v  = __ldg((const float4*)Y1 + (size_t)k*zs + i);
        float4 sc = __ldg((const float4*)(scale+k*D2)+c4);
        float4 sh = __ldg((const float4*)(shift+k*D2)+c4);
        acc.x += a*fmaxf(fmaf(v.x,sc.x,sh.x),0.f);
        acc.y += a*fmaxf(fmaf(v.y,sc.y,sh.y),0.f);
        acc.z += a*fmaxf(fmaf(v.z,sc.z,sh.z),0.f);
        acc.w += a*fmaxf(fmaf(v.w,sc.w,sh.w),0.f);
    }
    ((float4*)Zc)[i] = acc;
}

__global__ void colstats_kernel(const float* __restrict__ X, int M, int C, size_t zstride,
                                float* __restrict__ s, float* __restrict__ q)
{
    int z = blockIdx.y;
    X += (size_t)z*zstride; s += (size_t)z*C; q += (size_t)z*C;
    int c = threadIdx.x;
    float ps=0.f, pq=0.f;
    for (int r=blockIdx.x; r<M; r+=gridDim.x){
        float v = X[(size_t)r*C+c];
        ps += v; pq += v*v;
    }
    atomicAdd(&s[c],ps); atomicAdd(&q[c],pq);
}

__global__ void finalize_kernel(const float* __restrict__ s, const float* __restrict__ q,
                                const float* __restrict__ g, const float* __restrict__ b,
                                float* __restrict__ scale, float* __restrict__ shift,
                                float invN, int C)
{
    int k = blockIdx.x, c = threadIdx.x;
    float mu = s[k*C+c]*invN;
    float var = q[k*C+c]*invN - mu*mu;
    float rstd = rsqrtf(var+1e-5f);
    float sc = rstd*g[c];
    scale[k*C+c] = sc;
    shift[k*C+c] = b[c]-mu*sc;
}

__global__ void bnrelu_kernel(const float* __restrict__ X, const float* __restrict__ scale,
                              const float* __restrict__ shift, float* __restrict__ Out, int n4)
{
    int i = blockIdx.x*blockDim.x+threadIdx.x;
    if (i >= n4) return;
    int c4 = i & 31;
    float4 v  = ((const float4*)X)[i];
    float4 sc = ((const float4*)scale)[c4];
    float4 sh = ((const float4*)shift)[c4];
    v.x=fmaxf(fmaf(v.x,sc.x,sh.x),0.f);
    v.y=fmaxf(fmaf(v.y,sc.y,sh.y),0.f);
    v.z=fmaxf(fmaf(v.z,sc.z,sh.z),0.f);
    v.w=fmaxf(fmaf(v.w,sc.w,sh.w),0.f);
    ((float4*)Out)[i] = v;
}

// ---------------------------------------------------------------------------
extern "C" void kernel_launch(void* const* d_in, const int* in_sizes, int n_in,
                              void* d_out, int out_size)
{
    const int*   x     = (const int*)  d_in[0];
    const int*   ke    = (const int*)  d_in[1];
    const float* emb   = (const float*)d_in[2];
    const float* W1    = (const float*)d_in[3];
    const float* b1    = (const float*)d_in[4];
    const float* g1    = (const float*)d_in[5];
    const float* be1   = (const float*)d_in[6];
    const float* W2    = (const float*)d_in[7];
    const float* b2    = (const float*)d_in[8];
    const float* eps   = (const float*)d_in[9];
    const float* alpha = (const float*)d_in[10];
    const float* bn_g  = (const float*)d_in[11];
    const float* bn_b  = (const float*)d_in[12];

    const int N = in_sizes[0]/NFEAT;
    const int E = in_sizes[1]/(KS*2);
    const int n4  = N*(D/4);
    const int n4b = N*(D2/4);
    const int nTilesM = (N+BM-1)/BM;

    float *p_h,*p_agg,*p_y1,*p_zc,*p_hacc,*p_sum,*p_sq,*p_scale,*p_shift,*p_aw;
    __nv_bfloat16 *p_w1h,*p_w1l,*p_w2h,*p_w2l;
    int *p_deg,*p_dcur,*p_rowptr,*p_csrc;
    cudaGetSymbolAddress((void**)&p_h,g_h);
    cudaGetSymbolAddress((void**)&p_agg,g_agg);
    cudaGetSymbolAddress((void**)&p_y1,g_y1);
    cudaGetSymbolAddress((void**)&p_zc,g_zc);
    cudaGetSymbolAddress((void**)&p_hacc,g_hacc);
    cudaGetSymbolAddress((void**)&p_sum,g_sum);
    cudaGetSymbolAddress((void**)&p_sq,g_sq);
    cudaGetSymbolAddress((void**)&p_scale,g_scale);
    cudaGetSymbolAddress((void**)&p_shift,g_shift);
    cudaGetSymbolAddress((void**)&p_aw,g_aw);
    cudaGetSymbolAddress((void**)&p_w1h,g_W1h);
    cudaGetSymbolAddress((void**)&p_w1l,g_W1l);
    cudaGetSymbolAddress((void**)&p_w2h,g_W2h);
    cudaGetSymbolAddress((void**)&p_w2l,g_W2l);
    cudaGetSymbolAddress((void**)&p_deg,g_deg);
    cudaGetSymbolAddress((void**)&p_dcur,g_dcur);
    cudaGetSymbolAddress((void**)&p_rowptr,g_rowptr);
    cudaGetSymbolAddress((void**)&p_csrc,g_csrc);

    cudaFuncSetAttribute(tgemm_kernel<D,  D2, true >,
                         cudaFuncAttributeMaxDynamicSharedMemorySize, SMEM_BYTES);
    cudaFuncSetAttribute(tgemm_kernel<D2, D,  false>,
                         cudaFuncAttributeMaxDynamicSharedMemorySize, SMEM_BYTES);

    const float invN = 1.0f/(float)N;

    {
        int tot = 2*LAY*D*D2;
        wsplit_kernel<<<(tot+255)/256, 256>>>(W1, W2, p_w1h, p_w1l, p_w2h, p_w2l);
    }
    // CSR build (once per launch; edge sets constant across layers)
    cudaMemsetAsync(p_deg, 0, (size_t)KS*N*sizeof(int));
    hist_kernel<<<(KS*E+255)/256, 256>>>(ke, p_deg, E, N);
    scan_kernel<<<KS, 1024>>>(p_deg, p_rowptr, p_dcur, N, E);
    fill_kernel<<<(KS*E+255)/256, 256>>>(ke, p_dcur, p_csrc, E, N);

    embed_kernel<<<(N*32+255)/256, 256>>>(x, emb, p_h, N);

    for (int l = 0; l < LAY; l++){
        softmax3_kernel<<<1,1>>>(alpha+l*KS, p_aw);

        // agg[z] = (1+eps)h + CSR-gathered neighbor sum (replaces scale_copy+scatter)
        aggregate_kernel<<<dim3((N*32+255)/256, KS), 256>>>(
            p_h, p_rowptr, p_csrc, eps+l, p_agg, N, E);

        // y1[z] = agg[z] @ W1 + b1
        tgemm_kernel<D, D2, true><<<dim3(nTilesM, 2, KS), 256, SMEM_BYTES>>>(
            p_agg, p_w1h+(size_t)l*D*D2, p_w1l+(size_t)l*D*D2, b1+l*D2, p_y1, N);

        cudaMemsetAsync(p_sum, 0, KS*D2*sizeof(float));
        cudaMemsetAsync(p_sq,  0, KS*D2*sizeof(float));
        colstats_kernel<<<dim3(1024,KS), D2>>>(p_y1, N, D2, (size_t)NPAD*D2, p_sum, p_sq);
        finalize_kernel<<<KS, D2>>>(p_sum, p_sq, g1+l*D2, be1+l*D2, p_scale, p_shift, invN, D2);

        combine_kernel<<<(n4b+255)/256, 256>>>(p_y1, p_scale, p_shift, p_aw, p_zc, n4b);

        tgemm_kernel<D2, D, false><<<dim3(nTilesM,1,1), 256, SMEM_BYTES>>>(
            p_zc, p_w2h+(size_t)l*D2*D, p_w2l+(size_t)l*D2*D, b2+l*D, p_hacc, N);

        cudaMemsetAsync(p_sum, 0, D*sizeof(float));
        cudaMemsetAsync(p_sq,  0, D*sizeof(float));
        colstats_kernel<<<dim3(2048,1), D>>>(p_hacc, N, D, 0, p_sum, p_sq);
        finalize_kernel<<<1, D>>>(p_sum, p_sq, bn_g+l*D, bn_b+l*D, p_scale, p_shift, invN, D);

        float* outp = (l == LAY-1) ? (float*)d_out : p_h;
        bnrelu_kernel<<<(n4+255)/256, 256>>>(p_hacc, p_scale, p_shift, outp, n4);
    }
}